// round 1
// baseline (speedup 1.0000x reference)
#include <cuda_runtime.h>
#include <math_constants.h>
#include <math.h>

// ---------------- problem constants ----------------
#define DD 6
#define HH 128
#define WW 128
#define CC 180
#define NHD 6
#define HDIM 30
#define NWIN 768           // (6/2)*(128/8)*(128/8)
#define NTOK 128           // 2*8*8
#define M_ROWS 98304       // NWIN*NTOK == DD*HH*WW
#define C3 540
#define C2 360
#define HID 360
#define ATT_SCALE 0.18257418583505536f   // 1/sqrt(30)

// ---------------- scratch (device globals; no allocs allowed) ----------------
__device__ float g_xw[M_ROWS * CC];        // LN1 + roll + window-partitioned activations
__device__ float g_qkvS[M_ROWS * C3];      // self qkv
__device__ float g_qkvM[M_ROWS * C3];      // mutual qkv
__device__ float g_xo[M_ROWS * C2];        // [mutual(180) | self(180)] attention outputs
__device__ float g_y[M_ROWS * CC];         // x + attention residual (image layout)
__device__ float g_h2[M_ROWS * CC];        // LN2(y)
__device__ float g_hid1[M_ROWS * HID];
__device__ float g_hid2[M_ROWS * HID];
__device__ float g_bias6[NHD * NTOK * NTOK];

// Map a window-partition row r (= win*128 + n) to its source/destination image
// token index. The -shift before partition and +shift after reverse cancel, so
// the same map is used for the LN1 gather and the proj scatter.
__device__ __forceinline__ int row_to_img(int r) {
    int win = r >> 7, n = r & 127;
    int dwin = win >> 8, rem = win & 255;
    int hwin = rem >> 4, wwin = rem & 15;
    int nd = n >> 6, nh = (n >> 3) & 7, nw = n & 7;
    int sd = dwin * 2 + nd + 1; if (sd >= 6) sd -= 6;
    int sh = (hwin * 8 + nh + 4) & 127;
    int sw = (wwin * 8 + nw + 4) & 127;
    return (sd * 128 + sh) * 128 + sw;
}

// ---------------- rel-pos bias gather: bias6[h][i][j] ----------------
__global__ void bias_kernel(const float* __restrict__ rpb, const int* __restrict__ rpi) {
    int idx = blockIdx.x * blockDim.x + threadIdx.x;
    if (idx >= NHD * NTOK * NTOK) return;
    int h = idx / (NTOK * NTOK), ij = idx % (NTOK * NTOK);
    g_bias6[idx] = rpb[rpi[ij] * NHD + h];
}

// ---------------- LayerNorm (warp per row). mode 0: gather via row_to_img ----------------
__global__ __launch_bounds__(256) void ln_kernel(const float* __restrict__ in,
                                                 float* __restrict__ outp,
                                                 const float* __restrict__ gg,
                                                 const float* __restrict__ bb,
                                                 int mode) {
    int gw = (blockIdx.x * blockDim.x + threadIdx.x) >> 5;
    int lane = threadIdx.x & 31;
    if (gw >= M_ROWS) return;
    int src = (mode == 0) ? row_to_img(gw) : gw;
    const float* rowp = in + (long)src * CC;
    float vals[6];
    float s = 0.f, ss = 0.f;
    int cnt = 0;
    for (int c = lane; c < CC; c += 32) { float v = rowp[c]; vals[cnt++] = v; s += v; ss += v * v; }
#pragma unroll
    for (int o = 16; o > 0; o >>= 1) {
        s  += __shfl_xor_sync(0xffffffffu, s, o);
        ss += __shfl_xor_sync(0xffffffffu, ss, o);
    }
    float mean = s * (1.f / CC);
    float var = ss * (1.f / CC) - mean * mean;
    float rstd = rsqrtf(var + 1e-5f);
    float* orow = outp + (long)gw * CC;
    cnt = 0;
    for (int c = lane; c < CC; c += 32)
        orow[c] = (vals[cnt++] - mean) * rstd * gg[c] + bb[c];
}

// ---------------- generic SGEMM: C[M,N] = A[M,K] @ B[K,N] + bias, with epilogues ----------------
// ADD_PB: A[r][k] += pb[(r%64)*180 + k]  (sine position bias for mutual qkv)
// MODE 0: store C
// MODE 1: proj scatter:  y[img(r)] = x[img(r)] + C        (Cout = y, addsrc = x)
// MODE 2: fc2 residual:  out[r]    = y[r] + C             (Cout = out, addsrc = y)
template <int ADD_PB, int MODE>
__global__ __launch_bounds__(256) void gemm_kernel(const float* __restrict__ A,
                                                   const float* __restrict__ B,
                                                   const float* __restrict__ bias,
                                                   float* __restrict__ Cout,
                                                   int K, int N,
                                                   const float* __restrict__ pb,
                                                   const float* __restrict__ addsrc) {
    __shared__ __align__(16) float As[16][68];
    __shared__ __align__(16) float Bs[16][64];
    int tid = threadIdx.x;
    int row0 = blockIdx.y * 64, n0 = blockIdx.x * 64;
    int tx = tid & 15, ty = tid >> 4;
    int lm = tid >> 4, lk = tid & 15;
    int bn = tid & 63, bk = tid >> 6;
    float acc[4][4] = {};
    int ktiles = (K + 15) >> 4;
    for (int kt = 0; kt < ktiles; kt++) {
        int k0 = kt << 4;
        int gk = k0 + lk;
#pragma unroll
        for (int ii = 0; ii < 4; ii++) {
            int m = lm + ii * 16;
            float v = 0.f;
            if (gk < K) {
                v = A[(long)(row0 + m) * K + gk];
                if (ADD_PB) v += pb[((row0 + m) & 63) * CC + gk];
            }
            As[lk][m] = v;
        }
#pragma unroll
        for (int ii = 0; ii < 4; ii++) {
            int kk = bk + ii * 4;
            int gkb = k0 + kk;
            float v = 0.f;
            if (gkb < K && n0 + bn < N) v = B[(long)gkb * N + n0 + bn];
            Bs[kk][bn] = v;
        }
        __syncthreads();
#pragma unroll
        for (int kk = 0; kk < 16; kk++) {
            float4 a4 = *(const float4*)&As[kk][ty * 4];
            float4 b4 = *(const float4*)&Bs[kk][tx * 4];
            float av[4] = {a4.x, a4.y, a4.z, a4.w};
            float bv[4] = {b4.x, b4.y, b4.z, b4.w};
#pragma unroll
            for (int i2 = 0; i2 < 4; i2++)
#pragma unroll
                for (int j = 0; j < 4; j++) acc[i2][j] += av[i2] * bv[j];
        }
        __syncthreads();
    }
#pragma unroll
    for (int i2 = 0; i2 < 4; i2++) {
        int r = row0 + ty * 4 + i2;
        int img = 0;
        if (MODE == 1) img = row_to_img(r);
#pragma unroll
        for (int j = 0; j < 4; j++) {
            int cn = n0 + tx * 4 + j;
            if (cn < N) {
                float v = acc[i2][j] + bias[cn];
                if (MODE == 0)      Cout[(long)r * N + cn] = v;
                else if (MODE == 1) Cout[(long)img * CC + cn] = addsrc[(long)img * CC + cn] + v;
                else                Cout[(long)r * CC + cn] = addsrc[(long)r * CC + cn] + v;
            }
        }
    }
}

// ---------------- self attention: block per (head, window), thread per query row ----------------
__global__ __launch_bounds__(128) void self_attn_kernel(const float* __restrict__ mask) {
    int h = blockIdx.x, w = blockIdx.y, i = threadIdx.x;
    extern __shared__ float sm[];
    float* Ks = sm;                  // 128*32
    float* Vs = sm + 128 * 32;       // 128*32
    float* S  = sm + 2 * 128 * 32;   // 128*129 (odd stride -> conflict-free)
    const float* base = g_qkvS + (long)w * NTOK * C3;
    const float* qrow = base + i * C3 + h * HDIM;
    float q[32];
#pragma unroll
    for (int t = 0; t < 32; t++) q[t] = 0.f;
#pragma unroll
    for (int d = 0; d < HDIM; d++) q[d] = qrow[d] * ATT_SCALE;
#pragma unroll
    for (int d = 0; d < HDIM; d++) { Ks[i * 32 + d] = qrow[180 + d]; Vs[i * 32 + d] = qrow[360 + d]; }
    Ks[i * 32 + 30] = 0.f; Ks[i * 32 + 31] = 0.f;
    Vs[i * 32 + 30] = 0.f; Vs[i * 32 + 31] = 0.f;
    __syncthreads();
    const float* brow = g_bias6 + h * (NTOK * NTOK) + i * NTOK;
    const float* mrow = mask + (long)w * (NTOK * NTOK) + i * NTOK;
    float* Srow = S + i * 129;
    float rmax = -CUDART_INF_F;
#pragma unroll 4
    for (int m = 0; m < 128; m++) {
        const float4* kp = (const float4*)(Ks + m * 32);
        float s = 0.f;
#pragma unroll
        for (int t = 0; t < 8; t++) {
            float4 kv = kp[t];
            s += q[4 * t] * kv.x + q[4 * t + 1] * kv.y + q[4 * t + 2] * kv.z + q[4 * t + 3] * kv.w;
        }
        s += brow[m] + mrow[m];
        Srow[m] = s;
        rmax = fmaxf(rmax, s);
    }
    float ssum = 0.f;
#pragma unroll 4
    for (int m = 0; m < 128; m++) { float p = __expf(Srow[m] - rmax); Srow[m] = p; ssum += p; }
    float inv = 1.f / ssum;
    float acc[32];
#pragma unroll
    for (int t = 0; t < 32; t++) acc[t] = 0.f;
#pragma unroll 2
    for (int m = 0; m < 128; m++) {
        float p = Srow[m];
        const float4* vp = (const float4*)(Vs + m * 32);
#pragma unroll
        for (int t = 0; t < 8; t++) {
            float4 vv = vp[t];
            acc[4 * t] += p * vv.x; acc[4 * t + 1] += p * vv.y;
            acc[4 * t + 2] += p * vv.z; acc[4 * t + 3] += p * vv.w;
        }
    }
    float* orow = g_xo + (long)(w * NTOK + i) * C2 + CC + h * HDIM;
#pragma unroll
    for (int d = 0; d < HDIM; d++) orow[d] = acc[d] * inv;
}

// ---------------- mutual attention: two 64x64 cross attentions per (head, window) ----------------
__global__ __launch_bounds__(128) void mut_attn_kernel(const float* __restrict__ mask) {
    int h = blockIdx.x, w = blockIdx.y;
    int tid = threadIdx.x;
    int g = tid >> 6, r = tid & 63;
    extern __shared__ float sm[];
    float* Ks = sm;                   // 2*64*32
    float* Vs = sm + 2 * 64 * 32;     // 2*64*32
    float* S  = sm + 4 * 64 * 32;     // 2*64*65
    const float* base = g_qkvM + (long)w * NTOK * C3;
    int tk = g * 64 + r;                       // keys/values: group0 <- tokens 0..63, group1 <- 64..127
    const float* krow = base + tk * C3 + 180 + h * HDIM;
    float* ksd = Ks + tk * 32;
    float* vsd = Vs + tk * 32;
#pragma unroll
    for (int d = 0; d < HDIM; d++) { ksd[d] = krow[d]; vsd[d] = krow[180 + d]; }
    ksd[30] = ksd[31] = vsd[30] = vsd[31] = 0.f;
    int qt = (1 - g) * 64 + r;                 // group0 uses q2 (64..127), group1 uses q1 (0..63)
    const float* qrow = base + qt * C3 + h * HDIM;
    float q[32];
#pragma unroll
    for (int t = 0; t < 32; t++) q[t] = 0.f;
#pragma unroll
    for (int d = 0; d < HDIM; d++) q[d] = qrow[d] * ATT_SCALE;
    __syncthreads();
    const float* mrow = mask + (long)w * (NTOK * NTOK) + r * NTOK;   // m2 = mask[:, :64, :64]
    float* Srow = S + (g * 64 + r) * 65;
    const float* Kg = Ks + g * 64 * 32;
    const float* Vg = Vs + g * 64 * 32;
    float rmax = -CUDART_INF_F;
#pragma unroll 4
    for (int m = 0; m < 64; m++) {
        const float4* kp = (const float4*)(Kg + m * 32);
        float s = 0.f;
#pragma unroll
        for (int t = 0; t < 8; t++) {
            float4 kv = kp[t];
            s += q[4 * t] * kv.x + q[4 * t + 1] * kv.y + q[4 * t + 2] * kv.z + q[4 * t + 3] * kv.w;
        }
        s += mrow[m];
        Srow[m] = s;
        rmax = fmaxf(rmax, s);
    }
    float ssum = 0.f;
#pragma unroll 4
    for (int m = 0; m < 64; m++) { float p = __expf(Srow[m] - rmax); Srow[m] = p; ssum += p; }
    float inv = 1.f / ssum;
    float acc[32];
#pragma unroll
    for (int t = 0; t < 32; t++) acc[t] = 0.f;
#pragma unroll 2
    for (int m = 0; m < 64; m++) {
        float p = Srow[m];
        const float4* vp = (const float4*)(Vg + m * 32);
#pragma unroll
        for (int t = 0; t < 8; t++) {
            float4 vv = vp[t];
            acc[4 * t] += p * vv.x; acc[4 * t + 1] += p * vv.y;
            acc[4 * t + 2] += p * vv.z; acc[4 * t + 3] += p * vv.w;
        }
    }
    float* orow = g_xo + (long)(w * NTOK + g * 64 + r) * C2 + h * HDIM;
#pragma unroll
    for (int d = 0; d < HDIM; d++) orow[d] = acc[d] * inv;
}

// ---------------- GELU(exact) gate: hid1 = gelu(hid1) * hid2 ----------------
__global__ void gelu_mul_kernel() {
    int idx = blockIdx.x * blockDim.x + threadIdx.x;
    if (idx >= M_ROWS * HID) return;
    float v = g_hid1[idx];
    float gl = 0.5f * v * (1.f + erff(v * 0.7071067811865475f));
    g_hid1[idx] = gl * g_hid2[idx];
}

// ---------------- launcher ----------------
extern "C" void kernel_launch(void* const* d_in, const int* in_sizes, int n_in,
                              void* d_out, int out_size) {
    const float* x     = (const float*)d_in[0];
    const float* mask  = (const float*)d_in[1];
    const float* g1    = (const float*)d_in[2];
    const float* b1    = (const float*)d_in[3];
    const float* g2    = (const float*)d_in[4];
    const float* b2    = (const float*)d_in[5];
    const float* wqs   = (const float*)d_in[6];
    const float* bqs   = (const float*)d_in[7];
    const float* wqm   = (const float*)d_in[8];
    const float* bqm   = (const float*)d_in[9];
    const float* rpb   = (const float*)d_in[10];
    const float* posb  = (const float*)d_in[11];
    const float* wproj = (const float*)d_in[12];
    const float* bproj = (const float*)d_in[13];
    const float* w11   = (const float*)d_in[14];
    const float* b11   = (const float*)d_in[15];
    const float* w12   = (const float*)d_in[16];
    const float* b12   = (const float*)d_in[17];
    const float* w2    = (const float*)d_in[18];
    const float* b2f   = (const float*)d_in[19];
    const int*   rpi   = (const int*)d_in[20];
    float* out = (float*)d_out;

    float *p_xw, *p_qkvS, *p_qkvM, *p_xo, *p_y, *p_h2, *p_hid1, *p_hid2;
    cudaGetSymbolAddress((void**)&p_xw,   g_xw);
    cudaGetSymbolAddress((void**)&p_qkvS, g_qkvS);
    cudaGetSymbolAddress((void**)&p_qkvM, g_qkvM);
    cudaGetSymbolAddress((void**)&p_xo,   g_xo);
    cudaGetSymbolAddress((void**)&p_y,    g_y);
    cudaGetSymbolAddress((void**)&p_h2,   g_h2);
    cudaGetSymbolAddress((void**)&p_hid1, g_hid1);
    cudaGetSymbolAddress((void**)&p_hid2, g_hid2);

    const int SMEM_SELF = (2 * 128 * 32 + 128 * 129) * 4;   // 98816 B
    const int SMEM_MUT  = (4 * 64 * 32 + 2 * 64 * 65) * 4;  // 66048 B
    cudaFuncSetAttribute(self_attn_kernel, cudaFuncAttributeMaxDynamicSharedMemorySize, SMEM_SELF);
    cudaFuncSetAttribute(mut_attn_kernel,  cudaFuncAttributeMaxDynamicSharedMemorySize, SMEM_MUT);

    // 1) rel-pos bias table gather
    bias_kernel<<<(NHD * NTOK * NTOK + 255) / 256, 256>>>(rpb, rpi);
    // 2) LN1 + roll + window partition
    ln_kernel<<<(M_ROWS * 32) / 256, 256>>>(x, p_xw, g1, b1, 0);
    // 3) qkv GEMMs
    dim3 gq((C3 + 63) / 64, M_ROWS / 64);
    gemm_kernel<0, 0><<<gq, 256>>>(p_xw, wqs, bqs, p_qkvS, CC, C3, nullptr, nullptr);
    gemm_kernel<1, 0><<<gq, 256>>>(p_xw, wqm, bqm, p_qkvM, CC, C3, posb, nullptr);
    // 4) attention
    dim3 ga(NHD, NWIN);
    self_attn_kernel<<<ga, 128, SMEM_SELF>>>(mask);
    mut_attn_kernel<<<ga, 128, SMEM_MUT>>>(mask);
    // 5) proj + window reverse + roll + residual -> y
    dim3 gp((CC + 63) / 64, M_ROWS / 64);
    gemm_kernel<0, 1><<<gp, 256>>>(p_xo, wproj, bproj, p_y, C2, CC, nullptr, x);
    // 6) LN2
    ln_kernel<<<(M_ROWS * 32) / 256, 256>>>(p_y, p_h2, g2, b2, 1);
    // 7) MLP
    dim3 gf((HID + 63) / 64, M_ROWS / 64);
    gemm_kernel<0, 0><<<gf, 256>>>(p_h2, w11, b11, p_hid1, CC, HID, nullptr, nullptr);
    gemm_kernel<0, 0><<<gf, 256>>>(p_h2, w12, b12, p_hid2, CC, HID, nullptr, nullptr);
    gelu_mul_kernel<<<(M_ROWS * HID + 255) / 256, 256>>>();
    gemm_kernel<0, 2><<<gp, 256>>>(p_hid1, w2, b2f, out, HID, CC, nullptr, p_y);
}

// round 5
// speedup vs baseline: 1.7292x; 1.7292x over previous
#include <cuda_runtime.h>
#include <cuda_fp16.h>
#include <mma.h>
#include <cstdint>
#include <math_constants.h>
#include <math.h>

using namespace nvcuda;

// ---------------- problem constants ----------------
#define DD 6
#define HH 128
#define WW 128
#define CC 180
#define NHD 6
#define HDIM 30
#define NWIN 768
#define NTOK 128
#define M_ROWS 98304
#define C3 540
#define C2 360
#define HID 360
#define ATT_SCALE 0.18257418583505536f

// ---------------- scratch (device globals; allocs are banned) ----------------
__device__ float g_xw[M_ROWS * CC];
__device__ float g_qkvS[M_ROWS * C3];
__device__ float g_qkvM[M_ROWS * C3];
__device__ float g_xo[M_ROWS * C2];
__device__ float g_y[M_ROWS * CC];
__device__ float g_h2[M_ROWS * CC];
__device__ float g_hid1[M_ROWS * HID];
__device__ float g_hid2[M_ROWS * HID];
__device__ float g_bias6[NHD * NTOK * NTOK];
// fp16 transposed+padded weights: [Npad, Kpad]
__device__ __half g_wT_qs[576 * 192];
__device__ __half g_wT_qm[576 * 192];
__device__ __half g_wT_pr[192 * 384];
__device__ __half g_wT_f11[384 * 192];
__device__ __half g_wT_f12[384 * 192];
__device__ __half g_wT_f2[192 * 384];

// device-side buffer selectors (constexpr-folded)
template <int ID> __device__ __forceinline__ float* fbuf() {
    if (ID == 0) return g_xw;
    if (ID == 1) return g_qkvS;
    if (ID == 2) return g_qkvM;
    if (ID == 3) return g_xo;
    if (ID == 4) return g_y;
    if (ID == 5) return g_h2;
    if (ID == 6) return g_hid1;
    return g_hid2;
}
template <int ID> __device__ __forceinline__ __half* wbuf() {
    if (ID == 0) return g_wT_qs;
    if (ID == 1) return g_wT_qm;
    if (ID == 2) return g_wT_pr;
    if (ID == 3) return g_wT_f11;
    if (ID == 4) return g_wT_f12;
    return g_wT_f2;
}

__device__ __forceinline__ int row_to_img(int r) {
    int win = r >> 7, n = r & 127;
    int dwin = win >> 8, rem = win & 255;
    int hwin = rem >> 4, wwin = rem & 15;
    int nd = n >> 6, nh = (n >> 3) & 7, nw = n & 7;
    int sd = dwin * 2 + nd + 1; if (sd >= 6) sd -= 6;
    int sh = (hwin * 8 + nh + 4) & 127;
    int sw = (wwin * 8 + nw + 4) & 127;
    return (sd * 128 + sh) * 128 + sw;
}

// ---------------- weight prep: fp16 transpose + pad ----------------
template <int WID>
__global__ void prep_w_kernel(const float* __restrict__ w, int K, int N, int Kpad, int Npad) {
    __half* wt = wbuf<WID>();
    int idx = blockIdx.x * blockDim.x + threadIdx.x;
    if (idx >= Npad * Kpad) return;
    int n = idx / Kpad, k = idx % Kpad;
    wt[idx] = (n < N && k < K) ? __float2half(w[(long)k * N + n]) : __float2half(0.f);
}

// ---------------- rel-pos bias gather ----------------
__global__ void bias_kernel(const float* __restrict__ rpb, const int* __restrict__ rpi) {
    int idx = blockIdx.x * blockDim.x + threadIdx.x;
    if (idx >= NHD * NTOK * NTOK) return;
    int h = idx / (NTOK * NTOK), ij = idx % (NTOK * NTOK);
    g_bias6[idx] = rpb[rpi[ij] * NHD + h];
}

// ---------------- LayerNorm ----------------
template <int MODE>
__global__ __launch_bounds__(256) void ln_kernel(const float* __restrict__ in,
                                                 const float* __restrict__ gg,
                                                 const float* __restrict__ bb) {
    const float* src_buf = (MODE == 0) ? in : fbuf<4>();
    float* dst_buf = (MODE == 0) ? fbuf<0>() : fbuf<5>();
    int gw = (blockIdx.x * blockDim.x + threadIdx.x) >> 5;
    int lane = threadIdx.x & 31;
    if (gw >= M_ROWS) return;
    int srcrow = (MODE == 0) ? row_to_img(gw) : gw;
    const float* rowp = src_buf + (long)srcrow * CC;
    float vals[6];
    float s = 0.f, ss = 0.f;
    int cnt = 0;
    for (int c = lane; c < CC; c += 32) { float v = rowp[c]; vals[cnt++] = v; s += v; ss += v * v; }
#pragma unroll
    for (int o = 16; o > 0; o >>= 1) {
        s  += __shfl_xor_sync(0xffffffffu, s, o);
        ss += __shfl_xor_sync(0xffffffffu, ss, o);
    }
    float mean = s * (1.f / CC);
    float var = ss * (1.f / CC) - mean * mean;
    float rstd = rsqrtf(var + 1e-5f);
    float* orow = dst_buf + (long)gw * CC;
    cnt = 0;
    for (int c = lane; c < CC; c += 32)
        orow[c] = (vals[cnt++] - mean) * rstd * gg[c] + bb[c];
}

// ---------------- wmma fp16 GEMM (HMMA tensor cores; baseline PTX, no tcgen05) ----
// C[M_ROWS, Nreal] = A[M_ROWS, Kreal] @ W^T + bias, epilogue by MODE.
// SRC: fbuf id of A. DST: fbuf id of C (or -1 -> CoutExt). WID: weight id [Npad][KPAD].
// MODE 0: store. MODE 1: y[img] = extA[img] + v (proj scatter). MODE 2: out[r] = g_y[r] + v.
template <int KPAD, int ADD_PB, int MODE, int SRC, int DST, int WID>
__global__ __launch_bounds__(256) void gemm_wmma(const float* __restrict__ bias,
                                                 float* __restrict__ CoutExt,
                                                 const float* __restrict__ extA,
                                                 const float* __restrict__ pb,
                                                 int Kreal, int Nreal, int Ntiles) {
    const float* A = fbuf<SRC>();
    const __half* BT = wbuf<WID>();
    float* Cout = (DST >= 0) ? fbuf<(DST >= 0 ? DST : 0)>() : CoutExt;
    const float* addsrc = (MODE == 1) ? extA : fbuf<4>();

    constexpr int LDA = KPAD + 8;               // half elements per smem row
    constexpr int LDC = 68;                     // float elements per C smem row
    extern __shared__ __align__(16) char smem[];
    __half* As = (__half*)smem;                 // [128][LDA]
    __half* Bs = As + 128 * LDA;                // [64][LDA]
    float*  Cs = (float*)(Bs + 64 * LDA);       // [128][LDC]

    int tid = threadIdx.x, wid = tid >> 5;
    int m0 = blockIdx.x * 128;

    // ---- stage A tile [128][KPAD] fp16 (zero-padded beyond Kreal) ----
    constexpr int KF4 = KPAD / 4;
    int kreal4 = Kreal >> 2;
    for (int idx = tid; idx < 128 * KF4; idx += 256) {
        int row = idx / KF4, c4 = idx % KF4;
        uint2 val = make_uint2(0u, 0u);
        if (c4 < kreal4) {
            float4 a = *(const float4*)(A + (long)(m0 + row) * Kreal + c4 * 4);
            if (ADD_PB) {
                float4 p = *(const float4*)(pb + ((m0 + row) & 63) * CC + c4 * 4);
                a.x += p.x; a.y += p.y; a.z += p.z; a.w += p.w;
            }
            __half2 h0 = __floats2half2_rn(a.x, a.y);
            __half2 h1 = __floats2half2_rn(a.z, a.w);
            val.x = *(uint32_t*)&h0;
            val.y = *(uint32_t*)&h1;
        }
        *(uint2*)(As + row * LDA + c4 * 4) = val;
    }

    int wm = (wid & 3) * 32;   // warp row offset within 128
    int wn = (wid >> 2) * 32;  // warp col offset within 64

    for (int t = 0; t < Ntiles; t++) {
        int n0 = t * 64;
        // ---- stage B tile [64][KPAD] fp16 ----
        constexpr int BU4 = KPAD / 8;
        for (int idx = tid; idx < 64 * BU4; idx += 256) {
            int n = idx / BU4, c = idx % BU4;
            uint4 v = *(const uint4*)(BT + (long)(n0 + n) * KPAD + c * 8);
            *(uint4*)(Bs + n * LDA + c * 8) = v;
        }
        __syncthreads();

        wmma::fragment<wmma::accumulator, 16, 16, 16, float> acc[2][2];
#pragma unroll
        for (int i = 0; i < 2; i++)
#pragma unroll
            for (int j = 0; j < 2; j++) wmma::fill_fragment(acc[i][j], 0.f);

#pragma unroll
        for (int k = 0; k < KPAD; k += 16) {
            wmma::fragment<wmma::matrix_a, 16, 16, 16, __half, wmma::row_major> af[2];
            wmma::fragment<wmma::matrix_b, 16, 16, 16, __half, wmma::col_major> bf[2];
#pragma unroll
            for (int i = 0; i < 2; i++)
                wmma::load_matrix_sync(af[i], As + (wm + i * 16) * LDA + k, LDA);
#pragma unroll
            for (int j = 0; j < 2; j++)
                wmma::load_matrix_sync(bf[j], Bs + (wn + j * 16) * LDA + k, LDA);
#pragma unroll
            for (int i = 0; i < 2; i++)
#pragma unroll
                for (int j = 0; j < 2; j++)
                    wmma::mma_sync(acc[i][j], af[i], bf[j], acc[i][j]);
        }

#pragma unroll
        for (int i = 0; i < 2; i++)
#pragma unroll
            for (int j = 0; j < 2; j++)
                wmma::store_matrix_sync(Cs + (wm + i * 16) * LDC + wn + j * 16,
                                        acc[i][j], LDC, wmma::mem_row_major);
        __syncthreads();

        // ---- epilogue: 128 rows x 64 cols ----
        for (int idx = tid; idx < 128 * 16; idx += 256) {
            int row = idx >> 4, c4 = (idx & 15) * 4;
            int n = n0 + c4;
            if (n + 4 <= Nreal) {
                float4 v = *(float4*)(Cs + row * LDC + c4);
                const float4 bv = *(const float4*)(bias + n);
                v.x += bv.x; v.y += bv.y; v.z += bv.z; v.w += bv.w;
                int r = m0 + row;
                if (MODE == 0) {
                    *(float4*)(Cout + (long)r * Nreal + n) = v;
                } else if (MODE == 1) {
                    int img = row_to_img(r);
                    const float4 xr = *(const float4*)(addsrc + (long)img * CC + n);
                    v.x += xr.x; v.y += xr.y; v.z += xr.z; v.w += xr.w;
                    *(float4*)(Cout + (long)img * CC + n) = v;
                } else {
                    const float4 yr = *(const float4*)(addsrc + (long)r * CC + n);
                    v.x += yr.x; v.y += yr.y; v.z += yr.z; v.w += yr.w;
                    *(float4*)(Cout + (long)r * CC + n) = v;
                }
            }
        }
        __syncthreads();
    }
}

// ---------------- self attention ----------------
__global__ __launch_bounds__(128) void self_attn_kernel(const float* __restrict__ mask) {
    int h = blockIdx.x, w = blockIdx.y, i = threadIdx.x;
    extern __shared__ float sm[];
    float* Ks = sm;
    float* Vs = sm + 128 * 32;
    float* S  = sm + 2 * 128 * 32;
    const float* base = g_qkvS + (long)w * NTOK * C3;
    const float* qrow = base + i * C3 + h * HDIM;
    float q[32];
#pragma unroll
    for (int t = 0; t < 32; t++) q[t] = 0.f;
#pragma unroll
    for (int d = 0; d < HDIM; d++) q[d] = qrow[d] * ATT_SCALE;
#pragma unroll
    for (int d = 0; d < HDIM; d++) { Ks[i * 32 + d] = qrow[180 + d]; Vs[i * 32 + d] = qrow[360 + d]; }
    Ks[i * 32 + 30] = 0.f; Ks[i * 32 + 31] = 0.f;
    Vs[i * 32 + 30] = 0.f; Vs[i * 32 + 31] = 0.f;
    __syncthreads();
    const float* brow = g_bias6 + h * (NTOK * NTOK) + i * NTOK;
    const float* mrow = mask + (long)w * (NTOK * NTOK) + i * NTOK;
    float* Srow = S + i * 129;
    float rmax = -CUDART_INF_F;
#pragma unroll 4
    for (int m = 0; m < 128; m++) {
        const float4* kp = (const float4*)(Ks + m * 32);
        float s = 0.f;
#pragma unroll
        for (int t = 0; t < 8; t++) {
            float4 kv = kp[t];
            s += q[4 * t] * kv.x + q[4 * t + 1] * kv.y + q[4 * t + 2] * kv.z + q[4 * t + 3] * kv.w;
        }
        s += brow[m] + mrow[m];
        Srow[m] = s;
        rmax = fmaxf(rmax, s);
    }
    float ssum = 0.f;
#pragma unroll 4
    for (int m = 0; m < 128; m++) { float p = __expf(Srow[m] - rmax); Srow[m] = p; ssum += p; }
    float inv = 1.f / ssum;
    float acc[32];
#pragma unroll
    for (int t = 0; t < 32; t++) acc[t] = 0.f;
#pragma unroll 2
    for (int m = 0; m < 128; m++) {
        float p = Srow[m];
        const float4* vp = (const float4*)(Vs + m * 32);
#pragma unroll
        for (int t = 0; t < 8; t++) {
            float4 vv = vp[t];
            acc[4 * t] += p * vv.x; acc[4 * t + 1] += p * vv.y;
            acc[4 * t + 2] += p * vv.z; acc[4 * t + 3] += p * vv.w;
        }
    }
    float* orow = g_xo + (long)(w * NTOK + i) * C2 + CC + h * HDIM;
#pragma unroll
    for (int d = 0; d < HDIM; d++) orow[d] = acc[d] * inv;
}

// ---------------- mutual attention ----------------
__global__ __launch_bounds__(128) void mut_attn_kernel(const float* __restrict__ mask) {
    int h = blockIdx.x, w = blockIdx.y;
    int tid = threadIdx.x;
    int g = tid >> 6, r = tid & 63;
    extern __shared__ float sm[];
    float* Ks = sm;
    float* Vs = sm + 2 * 64 * 32;
    float* S  = sm + 4 * 64 * 32;
    const float* base = g_qkvM + (long)w * NTOK * C3;
    int tk = g * 64 + r;
    const float* krow = base + tk * C3 + 180 + h * HDIM;
    float* ksd = Ks + tk * 32;
    float* vsd = Vs + tk * 32;
#pragma unroll
    for (int d = 0; d < HDIM; d++) { ksd[d] = krow[d]; vsd[d] = krow[180 + d]; }
    ksd[30] = ksd[31] = vsd[30] = vsd[31] = 0.f;
    int qt = (1 - g) * 64 + r;
    const float* qrow = base + qt * C3 + h * HDIM;
    float q[32];
#pragma unroll
    for (int t = 0; t < 32; t++) q[t] = 0.f;
#pragma unroll
    for (int d = 0; d < HDIM; d++) q[d] = qrow[d] * ATT_SCALE;
    __syncthreads();
    const float* mrow = mask + (long)w * (NTOK * NTOK) + r * NTOK;
    float* Srow = S + (g * 64 + r) * 65;
    const float* Kg = Ks + g * 64 * 32;
    const float* Vg = Vs + g * 64 * 32;
    float rmax = -CUDART_INF_F;
#pragma unroll 4
    for (int m = 0; m < 64; m++) {
        const float4* kp = (const float4*)(Kg + m * 32);
        float s = 0.f;
#pragma unroll
        for (int t = 0; t < 8; t++) {
            float4 kv = kp[t];
            s += q[4 * t] * kv.x + q[4 * t + 1] * kv.y + q[4 * t + 2] * kv.z + q[4 * t + 3] * kv.w;
        }
        s += mrow[m];
        Srow[m] = s;
        rmax = fmaxf(rmax, s);
    }
    float ssum = 0.f;
#pragma unroll 4
    for (int m = 0; m < 64; m++) { float p = __expf(Srow[m] - rmax); Srow[m] = p; ssum += p; }
    float inv = 1.f / ssum;
    float acc[32];
#pragma unroll
    for (int t = 0; t < 32; t++) acc[t] = 0.f;
#pragma unroll 2
    for (int m = 0; m < 64; m++) {
        float p = Srow[m];
        const float4* vp = (const float4*)(Vg + m * 32);
#pragma unroll
        for (int t = 0; t < 8; t++) {
            float4 vv = vp[t];
            acc[4 * t] += p * vv.x; acc[4 * t + 1] += p * vv.y;
            acc[4 * t + 2] += p * vv.z; acc[4 * t + 3] += p * vv.w;
        }
    }
    float* orow = g_xo + (long)(w * NTOK + g * 64 + r) * C2 + h * HDIM;
#pragma unroll
    for (int d = 0; d < HDIM; d++) orow[d] = acc[d] * inv;
}

// ---------------- GELU gate ----------------
__global__ void gelu_mul_kernel() {
    int idx = blockIdx.x * blockDim.x + threadIdx.x;
    if (idx >= M_ROWS * HID) return;
    float v = g_hid1[idx];
    float gl = 0.5f * v * (1.f + erff(v * 0.7071067811865475f));
    g_hid1[idx] = gl * g_hid2[idx];
}

// ---------------- launcher ----------------
extern "C" void kernel_launch(void* const* d_in, const int* in_sizes, int n_in,
                              void* d_out, int out_size) {
    const float* x     = (const float*)d_in[0];
    const float* mask  = (const float*)d_in[1];
    const float* g1    = (const float*)d_in[2];
    const float* b1    = (const float*)d_in[3];
    const float* g2    = (const float*)d_in[4];
    const float* b2    = (const float*)d_in[5];
    const float* wqs   = (const float*)d_in[6];
    const float* bqs   = (const float*)d_in[7];
    const float* wqm   = (const float*)d_in[8];
    const float* bqm   = (const float*)d_in[9];
    const float* rpb   = (const float*)d_in[10];
    const float* posb  = (const float*)d_in[11];
    const float* wproj = (const float*)d_in[12];
    const float* bproj = (const float*)d_in[13];
    const float* w11   = (const float*)d_in[14];
    const float* b11   = (const float*)d_in[15];
    const float* w12   = (const float*)d_in[16];
    const float* b12   = (const float*)d_in[17];
    const float* w2    = (const float*)d_in[18];
    const float* b2f   = (const float*)d_in[19];
    const int*   rpi   = (const int*)d_in[20];
    float* out = (float*)d_out;

    const int SMEM_SELF = (2 * 128 * 32 + 128 * 129) * 4;
    const int SMEM_MUT  = (4 * 64 * 32 + 2 * 64 * 65) * 4;
    const int SMEM_G192 = (128 * 200 + 64 * 200) * 2 + 128 * 68 * 4;  // 111616
    const int SMEM_G384 = (128 * 392 + 64 * 392) * 2 + 128 * 68 * 4;  // 185344

    cudaFuncSetAttribute(self_attn_kernel, cudaFuncAttributeMaxDynamicSharedMemorySize, SMEM_SELF);
    cudaFuncSetAttribute(mut_attn_kernel,  cudaFuncAttributeMaxDynamicSharedMemorySize, SMEM_MUT);
    cudaFuncSetAttribute(&gemm_wmma<192, 0, 0, 0, 1, 0>, cudaFuncAttributeMaxDynamicSharedMemorySize, SMEM_G192);
    cudaFuncSetAttribute(&gemm_wmma<192, 1, 0, 0, 2, 1>, cudaFuncAttributeMaxDynamicSharedMemorySize, SMEM_G192);
    cudaFuncSetAttribute(&gemm_wmma<384, 0, 1, 3, 4, 2>, cudaFuncAttributeMaxDynamicSharedMemorySize, SMEM_G384);
    cudaFuncSetAttribute(&gemm_wmma<192, 0, 0, 5, 6, 3>, cudaFuncAttributeMaxDynamicSharedMemorySize, SMEM_G192);
    cudaFuncSetAttribute(&gemm_wmma<192, 0, 0, 5, 7, 4>, cudaFuncAttributeMaxDynamicSharedMemorySize, SMEM_G192);
    cudaFuncSetAttribute(&gemm_wmma<384, 0, 2, 6, -1, 5>, cudaFuncAttributeMaxDynamicSharedMemorySize, SMEM_G384);

    // 0) weight prep (fp16 transpose + pad)
    prep_w_kernel<0><<<(576 * 192 + 255) / 256, 256>>>(wqs,   CC,  C3,  192, 576);
    prep_w_kernel<1><<<(576 * 192 + 255) / 256, 256>>>(wqm,   CC,  C3,  192, 576);
    prep_w_kernel<2><<<(192 * 384 + 255) / 256, 256>>>(wproj, C2,  CC,  384, 192);
    prep_w_kernel<3><<<(384 * 192 + 255) / 256, 256>>>(w11,   CC,  HID, 192, 384);
    prep_w_kernel<4><<<(384 * 192 + 255) / 256, 256>>>(w12,   CC,  HID, 192, 384);
    prep_w_kernel<5><<<(192 * 384 + 255) / 256, 256>>>(w2,    HID, CC,  384, 192);
    // 1) rel-pos bias
    bias_kernel<<<(NHD * NTOK * NTOK + 255) / 256, 256>>>(rpb, rpi);
    // 2) LN1 + roll + window partition
    ln_kernel<0><<<(M_ROWS * 32) / 256, 256>>>(x, g1, b1);
    // 3) qkv GEMMs (HMMA)
    gemm_wmma<192, 0, 0, 0, 1, 0><<<768, 256, SMEM_G192>>>(bqs, nullptr, nullptr, nullptr, CC, C3, 9);
    gemm_wmma<192, 1, 0, 0, 2, 1><<<768, 256, SMEM_G192>>>(bqm, nullptr, nullptr, posb, CC, C3, 9);
    // 4) attention
    dim3 ga(NHD, NWIN);
    self_attn_kernel<<<ga, 128, SMEM_SELF>>>(mask);
    mut_attn_kernel<<<ga, 128, SMEM_MUT>>>(mask);
    // 5) proj + window reverse + roll + residual -> g_y
    gemm_wmma<384, 0, 1, 3, 4, 2><<<768, 256, SMEM_G384>>>(bproj, nullptr, x, nullptr, C2, CC, 3);
    // 6) LN2
    ln_kernel<1><<<(M_ROWS * 32) / 256, 256>>>(nullptr, g2, b2);
    // 7) MLP
    gemm_wmma<192, 0, 0, 5, 6, 3><<<768, 256, SMEM_G192>>>(b11, nullptr, nullptr, nullptr, CC, HID, 6);
    gemm_wmma<192, 0, 0, 5, 7, 4><<<768, 256, SMEM_G192>>>(b12, nullptr, nullptr, nullptr, CC, HID, 6);
    gelu_mul_kernel<<<(M_ROWS * HID + 255) / 256, 256>>>();
    gemm_wmma<384, 0, 2, 6, -1, 5><<<768, 256, SMEM_G384>>>(b2f, out, nullptr, nullptr, HID, CC, 3);
}

// round 6
// speedup vs baseline: 1.7529x; 1.0137x over previous
#include <cuda_runtime.h>
#include <cuda_fp16.h>
#include <mma.h>
#include <cstdint>
#include <math_constants.h>
#include <math.h>

using namespace nvcuda;

// ---------------- problem constants ----------------
#define DD 6
#define HH 128
#define WW 128
#define CC 180
#define NHD 6
#define HDIM 30
#define NWIN 768
#define NTOK 128
#define M_ROWS 98304
#define C3 540
#define C2 360
#define HID 360
#define ATT_SCALE 0.18257418583505536f

// ---------------- scratch (device globals; allocs are banned) ----------------
__device__ float g_xw[M_ROWS * CC];
__device__ float g_qkvS[M_ROWS * C3];
__device__ float g_qkvM[M_ROWS * C3];
__device__ float g_xo[M_ROWS * C2];
__device__ float g_y[M_ROWS * CC];
__device__ float g_h2[M_ROWS * CC];
__device__ float g_hid1[M_ROWS * HID];
__device__ float g_bias6[NHD * NTOK * NTOK];
// fp16 transposed+padded weights: [Npad, Kpad]
__device__ __half g_wT_qs[576 * 192];
__device__ __half g_wT_qm[576 * 192];
__device__ __half g_wT_pr[192 * 384];
__device__ __half g_wT_f11[384 * 192];
__device__ __half g_wT_f12[384 * 192];
__device__ __half g_wT_f2[192 * 384];

template <int ID> __device__ __forceinline__ float* fbuf() {
    if (ID == 0) return g_xw;
    if (ID == 1) return g_qkvS;
    if (ID == 2) return g_qkvM;
    if (ID == 3) return g_xo;
    if (ID == 4) return g_y;
    if (ID == 5) return g_h2;
    return g_hid1;
}
template <int ID> __device__ __forceinline__ __half* wbuf() {
    if (ID == 0) return g_wT_qs;
    if (ID == 1) return g_wT_qm;
    if (ID == 2) return g_wT_pr;
    if (ID == 3) return g_wT_f11;
    if (ID == 4) return g_wT_f12;
    return g_wT_f2;
}

__device__ __forceinline__ int row_to_img(int r) {
    int win = r >> 7, n = r & 127;
    int dwin = win >> 8, rem = win & 255;
    int hwin = rem >> 4, wwin = rem & 15;
    int nd = n >> 6, nh = (n >> 3) & 7, nw = n & 7;
    int sd = dwin * 2 + nd + 1; if (sd >= 6) sd -= 6;
    int sh = (hwin * 8 + nh + 4) & 127;
    int sw = (wwin * 8 + nw + 4) & 127;
    return (sd * 128 + sh) * 128 + sw;
}

// ---------------- weight prep: fp16 transpose + pad ----------------
template <int WID>
__global__ void prep_w_kernel(const float* __restrict__ w, int K, int N, int Kpad, int Npad) {
    __half* wt = wbuf<WID>();
    int idx = blockIdx.x * blockDim.x + threadIdx.x;
    if (idx >= Npad * Kpad) return;
    int n = idx / Kpad, k = idx % Kpad;
    wt[idx] = (n < N && k < K) ? __float2half(w[(long)k * N + n]) : __float2half(0.f);
}

// ---------------- rel-pos bias gather ----------------
__global__ void bias_kernel(const float* __restrict__ rpb, const int* __restrict__ rpi) {
    int idx = blockIdx.x * blockDim.x + threadIdx.x;
    if (idx >= NHD * NTOK * NTOK) return;
    int h = idx / (NTOK * NTOK), ij = idx % (NTOK * NTOK);
    g_bias6[idx] = rpb[rpi[ij] * NHD + h];
}

// ---------------- LayerNorm ----------------
template <int MODE>
__global__ __launch_bounds__(256) void ln_kernel(const float* __restrict__ in,
                                                 const float* __restrict__ gg,
                                                 const float* __restrict__ bb) {
    const float* src_buf = (MODE == 0) ? in : fbuf<4>();
    float* dst_buf = (MODE == 0) ? fbuf<0>() : fbuf<5>();
    int gw = (blockIdx.x * blockDim.x + threadIdx.x) >> 5;
    int lane = threadIdx.x & 31;
    if (gw >= M_ROWS) return;
    int srcrow = (MODE == 0) ? row_to_img(gw) : gw;
    const float* rowp = src_buf + (long)srcrow * CC;
    float vals[6];
    float s = 0.f, ss = 0.f;
    int cnt = 0;
    for (int c = lane; c < CC; c += 32) { float v = rowp[c]; vals[cnt++] = v; s += v; ss += v * v; }
#pragma unroll
    for (int o = 16; o > 0; o >>= 1) {
        s  += __shfl_xor_sync(0xffffffffu, s, o);
        ss += __shfl_xor_sync(0xffffffffu, ss, o);
    }
    float mean = s * (1.f / CC);
    float var = ss * (1.f / CC) - mean * mean;
    float rstd = rsqrtf(var + 1e-5f);
    float* orow = dst_buf + (long)gw * CC;
    cnt = 0;
    for (int c = lane; c < CC; c += 32)
        orow[c] = (vals[cnt++] - mean) * rstd * gg[c] + bb[c];
}

// ---------------- wmma fp16 GEMM ----------------
// MODE 0: C = A@W^T + bias  (full tiles store direct to global, bias pre-loaded into acc)
// MODE 1: y[img] = x[img] + (A@W^T + bias)   (proj scatter)
// MODE 2: out[r] = g_y[r] + (A@W^T + bias)   (fc2 residual)
// MODE 3: hid1[r] = gelu(A@W1^T + b1) * (A@W2^T + b2)   (fused MLP gate)
template <int KPAD, int ADD_PB, int MODE, int SRC, int DST, int WID, int WID2>
__global__ __launch_bounds__(256) void gemm_wmma(const float* __restrict__ bias,
                                                 const float* __restrict__ bias2,
                                                 float* __restrict__ CoutExt,
                                                 const float* __restrict__ extA,
                                                 const float* __restrict__ pb,
                                                 int Kreal, int Nreal, int Ntiles) {
    const float* A = fbuf<SRC>();
    const __half* BT1 = wbuf<WID>();
    const __half* BT2 = wbuf<WID2>();
    float* Cout = (DST >= 0) ? fbuf<(DST >= 0 ? DST : 0)>() : CoutExt;
    const float* addsrc = (MODE == 1) ? extA : fbuf<4>();
    constexpr int NPASS = (MODE == 3) ? 2 : 1;

    constexpr int LDA = KPAD + 8;
    constexpr int LDC = 68;
    extern __shared__ __align__(16) char smem[];
    __half* As = (__half*)smem;                       // [128][LDA]
    __half* Bs = As + 128 * LDA;                      // [64][LDA]
    float*  Cs = (float*)(Bs + 64 * LDA);             // [128][LDC]
    float*  Cs2 = (MODE == 3) ? (Cs + 128 * LDC) : Cs;
    float*  biasS = (MODE == 3) ? (Cs2 + 128 * LDC) : Cs;  // alias Cs when safe

    int tid = threadIdx.x, wid = tid >> 5;
    int m0 = blockIdx.x * 128;

    // ---- stage A tile [128][KPAD] fp16 ----
    constexpr int KF4 = KPAD / 4;
    int kreal4 = Kreal >> 2;
    for (int idx = tid; idx < 128 * KF4; idx += 256) {
        int row = idx / KF4, c4 = idx % KF4;
        uint2 val = make_uint2(0u, 0u);
        if (c4 < kreal4) {
            float4 a = *(const float4*)(A + (long)(m0 + row) * Kreal + c4 * 4);
            if (ADD_PB) {
                float4 p = *(const float4*)(pb + ((m0 + row) & 63) * CC + c4 * 4);
                a.x += p.x; a.y += p.y; a.z += p.z; a.w += p.w;
            }
            __half2 h0 = __floats2half2_rn(a.x, a.y);
            __half2 h1 = __floats2half2_rn(a.z, a.w);
            val.x = *(uint32_t*)&h0;
            val.y = *(uint32_t*)&h1;
        }
        *(uint2*)(As + row * LDA + c4 * 4) = val;
    }

    int wm = (wid & 3) * 32;
    int wn = (wid >> 2) * 32;

    for (int t = 0; t < Ntiles; t++) {
        int n0 = t * 64;
        bool full = (MODE == 0) && (n0 + 64 <= Nreal);

#pragma unroll
        for (int pass = 0; pass < NPASS; pass++) {
            const __half* Bp = (pass == 0) ? BT1 : BT2;
            const float* bp = (pass == 0) ? bias : bias2;
            float* Cdst = (pass == 0) ? Cs : Cs2;

            // fill replicated bias tile (16 rows x 64)
            for (int idx = tid; idx < 16 * 64; idx += 256) {
                int row = idx >> 6, c = idx & 63;
                biasS[row * LDC + c] = (n0 + c < Nreal) ? bp[n0 + c] : 0.f;
            }
            // stage B tile [64][KPAD]
            constexpr int BU4 = KPAD / 8;
            for (int idx = tid; idx < 64 * BU4; idx += 256) {
                int n = idx / BU4, c = idx % BU4;
                uint4 v = *(const uint4*)(Bp + (long)(n0 + n) * KPAD + c * 8);
                *(uint4*)(Bs + n * LDA + c * 8) = v;
            }
            __syncthreads();

            wmma::fragment<wmma::accumulator, 16, 16, 16, float> acc[2][2];
#pragma unroll
            for (int i = 0; i < 2; i++)
#pragma unroll
                for (int j = 0; j < 2; j++)
                    wmma::load_matrix_sync(acc[i][j], biasS + wn + j * 16, LDC, wmma::mem_row_major);

#pragma unroll
            for (int k = 0; k < KPAD; k += 16) {
                wmma::fragment<wmma::matrix_a, 16, 16, 16, __half, wmma::row_major> af[2];
                wmma::fragment<wmma::matrix_b, 16, 16, 16, __half, wmma::col_major> bf[2];
#pragma unroll
                for (int i = 0; i < 2; i++)
                    wmma::load_matrix_sync(af[i], As + (wm + i * 16) * LDA + k, LDA);
#pragma unroll
                for (int j = 0; j < 2; j++)
                    wmma::load_matrix_sync(bf[j], Bs + (wn + j * 16) * LDA + k, LDA);
#pragma unroll
                for (int i = 0; i < 2; i++)
#pragma unroll
                    for (int j = 0; j < 2; j++)
                        wmma::mma_sync(acc[i][j], af[i], bf[j], acc[i][j]);
            }

            if (full) {
#pragma unroll
                for (int i = 0; i < 2; i++)
#pragma unroll
                    for (int j = 0; j < 2; j++)
                        wmma::store_matrix_sync(Cout + (long)(m0 + wm + i * 16) * Nreal + n0 + wn + j * 16,
                                                acc[i][j], Nreal, wmma::mem_row_major);
            } else {
#pragma unroll
                for (int i = 0; i < 2; i++)
#pragma unroll
                    for (int j = 0; j < 2; j++)
                        wmma::store_matrix_sync(Cdst + (wm + i * 16) * LDC + wn + j * 16,
                                                acc[i][j], LDC, wmma::mem_row_major);
            }
            __syncthreads();
        }

        if (!full) {
            // staged epilogue (bias already folded into acc)
            for (int idx = tid; idx < 128 * 16; idx += 256) {
                int row = idx >> 4, c4 = (idx & 15) * 4;
                int n = n0 + c4;
                if (n + 4 <= Nreal) {
                    float4 v = *(float4*)(Cs + row * LDC + c4);
                    int r = m0 + row;
                    if (MODE == 0) {
                        *(float4*)(Cout + (long)r * Nreal + n) = v;
                    } else if (MODE == 1) {
                        int img = row_to_img(r);
                        const float4 xr = *(const float4*)(addsrc + (long)img * CC + n);
                        v.x += xr.x; v.y += xr.y; v.z += xr.z; v.w += xr.w;
                        *(float4*)(Cout + (long)img * CC + n) = v;
                    } else if (MODE == 2) {
                        const float4 yr = *(const float4*)(addsrc + (long)r * CC + n);
                        v.x += yr.x; v.y += yr.y; v.z += yr.z; v.w += yr.w;
                        *(float4*)(Cout + (long)r * CC + n) = v;
                    } else {
                        float4 v2 = *(float4*)(Cs2 + row * LDC + c4);
                        float4 o;
                        o.x = 0.5f * v.x * (1.f + erff(v.x * 0.70710678f)) * v2.x;
                        o.y = 0.5f * v.y * (1.f + erff(v.y * 0.70710678f)) * v2.y;
                        o.z = 0.5f * v.z * (1.f + erff(v.z * 0.70710678f)) * v2.z;
                        o.w = 0.5f * v.w * (1.f + erff(v.w * 0.70710678f)) * v2.w;
                        *(float4*)(Cout + (long)r * Nreal + n) = o;
                    }
                }
            }
            __syncthreads();
        }
    }
}

// ---------------- self attention: online softmax (no score matrix) ----------------
__global__ __launch_bounds__(128) void self_attn_kernel(const float* __restrict__ mask) {
    int h = blockIdx.x, w = blockIdx.y, i = threadIdx.x;
    __shared__ float Ks[128 * 32];
    __shared__ float Vs[128 * 32];
    const float* base = g_qkvS + (long)w * NTOK * C3;
    const float* qrow = base + i * C3 + h * HDIM;
    float q[32];
#pragma unroll
    for (int t = 0; t < 32; t++) q[t] = 0.f;
#pragma unroll
    for (int d = 0; d < HDIM; d++) q[d] = qrow[d] * ATT_SCALE;
#pragma unroll
    for (int d = 0; d < HDIM; d++) { Ks[i * 32 + d] = qrow[180 + d]; Vs[i * 32 + d] = qrow[360 + d]; }
    Ks[i * 32 + 30] = 0.f; Ks[i * 32 + 31] = 0.f;
    Vs[i * 32 + 30] = 0.f; Vs[i * 32 + 31] = 0.f;
    __syncthreads();
    const float* brow = g_bias6 + h * (NTOK * NTOK) + i * NTOK;
    const float* mrow = mask + (long)w * (NTOK * NTOK) + i * NTOK;
    float ssum = 0.f;
    float acc[32];
#pragma unroll
    for (int t = 0; t < 32; t++) acc[t] = 0.f;
#pragma unroll 2
    for (int m = 0; m < 128; m++) {
        const float4* kp = (const float4*)(Ks + m * 32);
        float s = 0.f;
#pragma unroll
        for (int t = 0; t < 8; t++) {
            float4 kv = kp[t];
            s += q[4 * t] * kv.x + q[4 * t + 1] * kv.y + q[4 * t + 2] * kv.z + q[4 * t + 3] * kv.w;
        }
        float p = __expf(s + brow[m] + mrow[m]);
        ssum += p;
        const float4* vp = (const float4*)(Vs + m * 32);
#pragma unroll
        for (int t = 0; t < 8; t++) {
            float4 vv = vp[t];
            acc[4 * t] += p * vv.x; acc[4 * t + 1] += p * vv.y;
            acc[4 * t + 2] += p * vv.z; acc[4 * t + 3] += p * vv.w;
        }
    }
    float inv = 1.f / ssum;
    float* orow = g_xo + (long)(w * NTOK + i) * C2 + CC + h * HDIM;
#pragma unroll
    for (int d = 0; d < HDIM; d++) orow[d] = acc[d] * inv;
}

// ---------------- mutual attention: online softmax ----------------
__global__ __launch_bounds__(128) void mut_attn_kernel(const float* __restrict__ mask) {
    int h = blockIdx.x, w = blockIdx.y;
    int tid = threadIdx.x;
    int g = tid >> 6, r = tid & 63;
    __shared__ float Ks[128 * 32];
    __shared__ float Vs[128 * 32];
    const float* base = g_qkvM + (long)w * NTOK * C3;
    int tk = g * 64 + r;
    const float* krow = base + tk * C3 + 180 + h * HDIM;
    float* ksd = Ks + tk * 32;
    float* vsd = Vs + tk * 32;
#pragma unroll
    for (int d = 0; d < HDIM; d++) { ksd[d] = krow[d]; vsd[d] = krow[180 + d]; }
    ksd[30] = ksd[31] = vsd[30] = vsd[31] = 0.f;
    int qt = (1 - g) * 64 + r;
    const float* qrow = base + qt * C3 + h * HDIM;
    float q[32];
#pragma unroll
    for (int t = 0; t < 32; t++) q[t] = 0.f;
#pragma unroll
    for (int d = 0; d < HDIM; d++) q[d] = qrow[d] * ATT_SCALE;
    __syncthreads();
    const float* mrow = mask + (long)w * (NTOK * NTOK) + r * NTOK;
    const float* Kg = Ks + g * 64 * 32;
    const float* Vg = Vs + g * 64 * 32;
    float ssum = 0.f;
    float acc[32];
#pragma unroll
    for (int t = 0; t < 32; t++) acc[t] = 0.f;
#pragma unroll 2
    for (int m = 0; m < 64; m++) {
        const float4* kp = (const float4*)(Kg + m * 32);
        float s = 0.f;
#pragma unroll
        for (int t = 0; t < 8; t++) {
            float4 kv = kp[t];
            s += q[4 * t] * kv.x + q[4 * t + 1] * kv.y + q[4 * t + 2] * kv.z + q[4 * t + 3] * kv.w;
        }
        float p = __expf(s + mrow[m]);
        ssum += p;
        const float4* vp = (const float4*)(Vg + m * 32);
#pragma unroll
        for (int t = 0; t < 8; t++) {
            float4 vv = vp[t];
            acc[4 * t] += p * vv.x; acc[4 * t + 1] += p * vv.y;
            acc[4 * t + 2] += p * vv.z; acc[4 * t + 3] += p * vv.w;
        }
    }
    float inv = 1.f / ssum;
    float* orow = g_xo + (long)(w * NTOK + g * 64 + r) * C2 + h * HDIM;
#pragma unroll
    for (int d = 0; d < HDIM; d++) orow[d] = acc[d] * inv;
}

// ---------------- launcher ----------------
extern "C" void kernel_launch(void* const* d_in, const int* in_sizes, int n_in,
                              void* d_out, int out_size) {
    const float* x     = (const float*)d_in[0];
    const float* mask  = (const float*)d_in[1];
    const float* g1    = (const float*)d_in[2];
    const float* b1    = (const float*)d_in[3];
    const float* g2    = (const float*)d_in[4];
    const float* b2    = (const float*)d_in[5];
    const float* wqs   = (const float*)d_in[6];
    const float* bqs   = (const float*)d_in[7];
    const float* wqm   = (const float*)d_in[8];
    const float* bqm   = (const float*)d_in[9];
    const float* rpb   = (const float*)d_in[10];
    const float* posb  = (const float*)d_in[11];
    const float* wproj = (const float*)d_in[12];
    const float* bproj = (const float*)d_in[13];
    const float* w11   = (const float*)d_in[14];
    const float* b11   = (const float*)d_in[15];
    const float* w12   = (const float*)d_in[16];
    const float* b12   = (const float*)d_in[17];
    const float* w2    = (const float*)d_in[18];
    const float* b2f   = (const float*)d_in[19];
    const int*   rpi   = (const int*)d_in[20];
    float* out = (float*)d_out;

    const int SMEM_G192  = (128 * 200 + 64 * 200) * 2 + 128 * 68 * 4;                    // 111616
    const int SMEM_G192F = (128 * 200 + 64 * 200) * 2 + 2 * 128 * 68 * 4 + 16 * 68 * 4; // 150784
    const int SMEM_G384  = (128 * 392 + 64 * 392) * 2 + 128 * 68 * 4;                    // 185344

    cudaFuncSetAttribute(&gemm_wmma<192, 0, 0, 0, 1, 0, 0>, cudaFuncAttributeMaxDynamicSharedMemorySize, SMEM_G192);
    cudaFuncSetAttribute(&gemm_wmma<192, 1, 0, 0, 2, 1, 0>, cudaFuncAttributeMaxDynamicSharedMemorySize, SMEM_G192);
    cudaFuncSetAttribute(&gemm_wmma<384, 0, 1, 3, 4, 2, 0>, cudaFuncAttributeMaxDynamicSharedMemorySize, SMEM_G384);
    cudaFuncSetAttribute(&gemm_wmma<192, 0, 3, 5, 6, 3, 4>, cudaFuncAttributeMaxDynamicSharedMemorySize, SMEM_G192F);
    cudaFuncSetAttribute(&gemm_wmma<384, 0, 2, 6, -1, 5, 0>, cudaFuncAttributeMaxDynamicSharedMemorySize, SMEM_G384);

    // 0) weight prep (fp16 transpose + pad)
    prep_w_kernel<0><<<(576 * 192 + 255) / 256, 256>>>(wqs,   CC,  C3,  192, 576);
    prep_w_kernel<1><<<(576 * 192 + 255) / 256, 256>>>(wqm,   CC,  C3,  192, 576);
    prep_w_kernel<2><<<(192 * 384 + 255) / 256, 256>>>(wproj, C2,  CC,  384, 192);
    prep_w_kernel<3><<<(384 * 192 + 255) / 256, 256>>>(w11,   CC,  HID, 192, 384);
    prep_w_kernel<4><<<(384 * 192 + 255) / 256, 256>>>(w12,   CC,  HID, 192, 384);
    prep_w_kernel<5><<<(192 * 384 + 255) / 256, 256>>>(w2,    HID, CC,  384, 192);
    // 1) rel-pos bias
    bias_kernel<<<(NHD * NTOK * NTOK + 255) / 256, 256>>>(rpb, rpi);
    // 2) LN1 + roll + window partition
    ln_kernel<0><<<(M_ROWS * 32) / 256, 256>>>(x, g1, b1);
    // 3) qkv GEMMs (HMMA, bias-init, direct store)
    gemm_wmma<192, 0, 0, 0, 1, 0, 0><<<768, 256, SMEM_G192>>>(bqs, nullptr, nullptr, nullptr, nullptr, CC, C3, 9);
    gemm_wmma<192, 1, 0, 0, 2, 1, 0><<<768, 256, SMEM_G192>>>(bqm, nullptr, nullptr, nullptr, posb, CC, C3, 9);
    // 4) attention (online softmax)
    dim3 ga(NHD, NWIN);
    self_attn_kernel<<<ga, 128>>>(mask);
    mut_attn_kernel<<<ga, 128>>>(mask);
    // 5) proj + window reverse + roll + residual -> g_y
    gemm_wmma<384, 0, 1, 3, 4, 2, 0><<<768, 256, SMEM_G384>>>(bproj, nullptr, nullptr, x, nullptr, C2, CC, 3);
    // 6) LN2
    ln_kernel<1><<<(M_ROWS * 32) / 256, 256>>>(nullptr, g2, b2);
    // 7) fused MLP: hid1 = gelu(h2@w11+b11) * (h2@w12+b12)
    gemm_wmma<192, 0, 3, 5, 6, 3, 4><<<768, 256, SMEM_G192F>>>(b11, b12, nullptr, nullptr, nullptr, CC, HID, 6);
    // 8) fc2 + residual -> out
    gemm_wmma<384, 0, 2, 6, -1, 5, 0><<<768, 256, SMEM_G384>>>(b2f, nullptr, out, nullptr, nullptr, HID, CC, 3);
}